// round 10
// baseline (speedup 1.0000x reference)
#include <cuda_runtime.h>
#include <math.h>

#define BB 4096
#define KK 8192
#define NTHR 256

// ---------------- scratch (no allocations allowed) ----------------
// Per-row partials: every row writes, so no init kernel needed.
__device__ double g_hard[BB];        // per-row (ls . targets_row)
__device__ double g_soft[BB];        // per-row (ls . S[label])
__device__ int    g_correct[BB];     // pred == label flag
__device__ int    g_label[BB];       // per-row label
__device__ float  g_mls[BB];         // per-row  max + log(sum exp(o - max))

// One block per row. Pass 1: argmax(o) [pred], argmax(t) [label], sum(t),
// sum(o*t). Pass 2 (fused): sum exp(o-max), dot(o, S[label]), sum(S[label]).
// Loss identity per row:  (log_softmax(o) . x) = (o . x) - (max + lse) * sum(x)
__global__ void __launch_bounds__(NTHR) k_rows(const float* __restrict__ outp,
                                               const float* __restrict__ targ,
                                               const float* __restrict__ S) {
    const int b   = blockIdx.x;
    const int tid = threadIdx.x;
    const float4* o4 = (const float4*)(outp + (size_t)b * KK);
    const float4* t4 = (const float4*)(targ + (size_t)b * KK);

    __shared__ float sf0[NTHR];
    __shared__ float sf1[NTHR];
    __shared__ float sf2[NTHR];
    __shared__ int   si0[NTHR];
    __shared__ int   si1[NTHR];
    __shared__ float s_bcast[4];   // [0]=omax [1]=sum_t [2]=sum_ot
    __shared__ int   s_bcast_i[2]; // [0]=pred [1]=label

    // ---- pass 1: max/argmax of o, max/argmax of t, sum_t, sum_ot ----
    float omax = -INFINITY; int oidx = 0;
    float tmax = -INFINITY; int tidx = 0;
    float sum_t = 0.f, sum_ot = 0.f;

    for (int i = tid; i < KK / 4; i += NTHR) {
        float4 o = o4[i];
        float4 t = t4[i];
        int base = i * 4;
        float ov[4] = {o.x, o.y, o.z, o.w};
        float tv[4] = {t.x, t.y, t.z, t.w};
#pragma unroll
        for (int j = 0; j < 4; j++) {
            float v = ov[j];
            if (v > omax) { omax = v; oidx = base + j; }
            float w = tv[j];
            if (w > tmax) { tmax = w; tidx = base + j; }
            sum_t  += w;
            sum_ot += v * w;
        }
    }

    // block argmax reduce (first-index tiebreak) for o and t
    sf0[tid] = omax; si0[tid] = oidx;
    sf1[tid] = tmax; si1[tid] = tidx;
    __syncthreads();
    for (int s = NTHR / 2; s > 0; s >>= 1) {
        if (tid < s) {
            float v = sf0[tid + s]; int ix = si0[tid + s];
            if (v > sf0[tid] || (v == sf0[tid] && ix < si0[tid])) { sf0[tid] = v; si0[tid] = ix; }
            v = sf1[tid + s]; ix = si1[tid + s];
            if (v > sf1[tid] || (v == sf1[tid] && ix < si1[tid])) { sf1[tid] = v; si1[tid] = ix; }
        }
        __syncthreads();
    }
    if (tid == 0) {
        s_bcast[0]   = sf0[0];
        s_bcast_i[0] = si0[0];   // pred
        s_bcast_i[1] = si1[0];   // label
    }
    __syncthreads();

    sf0[tid] = sum_t; sf1[tid] = sum_ot;
    __syncthreads();
    for (int s = NTHR / 2; s > 0; s >>= 1) {
        if (tid < s) { sf0[tid] += sf0[tid + s]; sf1[tid] += sf1[tid + s]; }
        __syncthreads();
    }
    if (tid == 0) { s_bcast[1] = sf0[0]; s_bcast[2] = sf1[0]; }
    __syncthreads();

    const float omax_b = s_bcast[0];
    const int   pred   = s_bcast_i[0];
    const int   label  = s_bcast_i[1];

    // ---- pass 2 (fused): sum exp(o-max), dot(o, S[label]), sum(S[label]) ----
    // o row expected L1-resident; S row comes from DRAM/L2.
    const float4* s4 = (const float4*)(S + (size_t)label * KK);
    float se = 0.f, dot_os = 0.f, sum_s = 0.f;
    for (int i = tid; i < KK / 4; i += NTHR) {
        float4 o  = o4[i];
        float4 sv = s4[i];
        se += expf(o.x - omax_b) + expf(o.y - omax_b) +
              expf(o.z - omax_b) + expf(o.w - omax_b);
        dot_os += o.x * sv.x + o.y * sv.y + o.z * sv.z + o.w * sv.w;
        sum_s  += sv.x + sv.y + sv.z + sv.w;
    }
    sf0[tid] = se; sf1[tid] = dot_os; sf2[tid] = sum_s;
    __syncthreads();
    for (int s = NTHR / 2; s > 0; s >>= 1) {
        if (tid < s) {
            sf0[tid] += sf0[tid + s];
            sf1[tid] += sf1[tid + s];
            sf2[tid] += sf2[tid + s];
        }
        __syncthreads();
    }

    if (tid == 0) {
        float sum_t_b  = s_bcast[1];
        float sum_ot_b = s_bcast[2];
        float se_b     = sf0[0];
        float dot_b    = sf1[0];
        float sums_b   = sf2[0];
        float mls      = omax_b + logf(se_b);

        g_hard[b]    = (double)sum_ot_b - (double)mls * (double)sum_t_b;
        g_soft[b]    = (double)dot_b   - (double)mls * (double)sums_b;
        g_label[b]   = label;
        g_mls[b]     = mls;
        g_correct[b] = (pred == label) ? 1 : 0;
    }
}

// ---------------- bulk state copy ----------------
// dst_st = out + 1 is 4-byte offset from 16B alignment. Peel first 3 floats
// so stores become STG.128; loads stay coalesced LDG.32 (LTS cap is
// path-independent). Tail iterations copy `count` (K floats).
#define COPY_BLOCKS 2368           // 148 SMs * 16 blocks
#define COPY_THR    256
__global__ void __launch_bounds__(COPY_THR) k_copy(const float* __restrict__ s_t,
                                                   const float* __restrict__ cnt,
                                                   float* __restrict__ dst_st,
                                                   float* __restrict__ dst_cnt) {
    const long long N  = (long long)KK * KK;      // 67108864
    const long long N4 = (N - 3) >> 2;            // aligned float4 stores

    long long gid    = (long long)blockIdx.x * COPY_THR + threadIdx.x;
    long long stride = (long long)COPY_BLOCKS * COPY_THR;

    if (gid == 0) {
        dst_st[0] = s_t[0];
        dst_st[1] = s_t[1];
        dst_st[2] = s_t[2];
    }

    float4* d4 = (float4*)(dst_st + 3);           // 16B-aligned
    const float* s = s_t + 3;
    for (long long i = gid; i < N4; i += stride) {
        long long k = i << 2;
        float4 v;
        v.x = s[k + 0];
        v.y = s[k + 1];
        v.z = s[k + 2];
        v.w = s[k + 3];
        d4[i] = v;
    }
    // remaining scalar tail elements
    for (long long k = 3 + (N4 << 2) + gid; k < N; k += stride)
        dst_st[k] = s_t[k];

    // count copy (K elements) spread across the grid
    for (long long k = gid; k < KK; k += stride)
        dst_cnt[k] = cnt[k];
}

// ---------------- fused sparse scatter + loss ----------------
// Small grid scans correct-flags (grid-stride); matching rows (~0-2 of 4096)
// get probs scatter-added into out_st. Block 0 additionally reduces the
// per-row loss partials and writes the scalar loss.
#define TAIL_BLOCKS 256
__global__ void __launch_bounds__(NTHR) k_tail(const float* __restrict__ outp,
                                               float* __restrict__ out_st,
                                               float* __restrict__ out_count,
                                               float* __restrict__ out_loss) {
    const int tid = threadIdx.x;

    // sparse scatter portion
    for (int b = blockIdx.x; b < BB; b += TAIL_BLOCKS) {
        if (!g_correct[b]) continue;          // uniform per block: no divergence
        int   lab = g_label[b];
        float mls = g_mls[b];
        const float* o = outp + (size_t)b * KK;
        float* dst = out_st + (size_t)lab * KK;
        for (int k = tid; k < KK; k += NTHR)
            atomicAdd(&dst[k], expf(o[k] - mls));
        if (tid == 0)
            atomicAdd(&out_count[lab], 1.0f);
    }

    // loss reduction in block 0
    if (blockIdx.x == 0) {
        __shared__ double sh[NTHR];
        __shared__ double ss[NTHR];
        double h = 0.0, s = 0.0;
        for (int i = tid; i < BB; i += NTHR) {
            h += g_hard[i];
            s += g_soft[i];
        }
        sh[tid] = h; ss[tid] = s;
        __syncthreads();
        for (int st = NTHR / 2; st > 0; st >>= 1) {
            if (tid < st) { sh[tid] += sh[tid + st]; ss[tid] += ss[tid + st]; }
            __syncthreads();
        }
        if (tid == 0) {
            double ce_hard = -sh[0] / (double)BB;
            double ce_soft = -ss[0] / (double)BB;
            out_loss[0] = (float)(0.5 * ce_hard + 0.5 * ce_soft);
        }
    }
}

extern "C" void kernel_launch(void* const* d_in, const int* in_sizes, int n_in,
                              void* d_out, int out_size) {
    const float* outputs = (const float*)d_in[0];   // [B, K]
    const float* targets = (const float*)d_in[1];   // [B, K] one-hot
    const float* S       = (const float*)d_in[2];   // [K, K]
    const float* S_t     = (const float*)d_in[3];   // [K, K]
    const float* count   = (const float*)d_in[4];   // [K, 1]

    float* out       = (float*)d_out;
    float* out_loss  = out;                              // [1]
    float* out_st    = out + 1;                          // [K*K]
    float* out_count = out + 1 + (size_t)KK * KK;        // [K]

    k_rows<<<BB, NTHR>>>(outputs, targets, S);
    k_copy<<<COPY_BLOCKS, COPY_THR>>>(S_t, count, out_st, out_count);
    k_tail<<<TAIL_BLOCKS, NTHR>>>(outputs, out_st, out_count, out_loss);
}

// round 11
// speedup vs baseline: 1.0886x; 1.0886x over previous
#include <cuda_runtime.h>
#include <math.h>

#define BB 4096
#define KK 8192
#define NTHR 256

// ---------------- scratch (no allocations allowed) ----------------
// Per-row loss partials: every row writes, no init kernel needed.
__device__ double g_hard[BB];        // per-row (ls . targets_row) = o[label] - mls
__device__ double g_soft[BB];        // per-row (ls . S[label])

// One block per row.
// Pass 1: omax = max(o) (pure fmax), label = index where one-hot t != 0.
// Then:  hard = o[label] - mls ;  correct = (o[label] == omax)  [pred==label].
// Pass 2: se = sum exp(o-omax), dot(o,S[label]), sum(S[label]).
// If correct: scatter probs into out_st (out_st pre-filled by k_copy).
__global__ void __launch_bounds__(NTHR) k_rows(const float* __restrict__ outp,
                                               const float* __restrict__ targ,
                                               const float* __restrict__ S,
                                               float* __restrict__ out_st,
                                               float* __restrict__ out_count) {
    const int b   = blockIdx.x;
    const int tid = threadIdx.x;
    const float4* o4 = (const float4*)(outp + (size_t)b * KK);
    const float4* t4 = (const float4*)(targ + (size_t)b * KK);

    __shared__ float sf0[NTHR];
    __shared__ float sf1[NTHR];
    __shared__ float sf2[NTHR];
    __shared__ int   s_label;
    __shared__ float s_omax;
    __shared__ float s_mls;
    __shared__ int   s_correct;

    // ---- pass 1: max(o) and label (index of the single nonzero in t) ----
    float omax = -INFINITY;
    for (int i = tid; i < KK / 4; i += NTHR) {
        float4 o = o4[i];
        float4 t = __ldcs(&t4[i]);           // stream: evict-first, keep o in L1
        omax = fmaxf(omax, fmaxf(fmaxf(o.x, o.y), fmaxf(o.z, o.w)));
        int base = i * 4;
        if (t.x != 0.f) s_label = base;
        if (t.y != 0.f) s_label = base + 1;
        if (t.z != 0.f) s_label = base + 2;
        if (t.w != 0.f) s_label = base + 3;
    }
    sf0[tid] = omax;
    __syncthreads();
    for (int s = NTHR / 2; s > 0; s >>= 1) {
        if (tid < s) sf0[tid] = fmaxf(sf0[tid], sf0[tid + s]);
        __syncthreads();
    }
    if (tid == 0) s_omax = sf0[0];
    __syncthreads();

    const int   label  = s_label;
    const float omax_b = s_omax;
    const float o_lab  = outp[(size_t)b * KK + label];  // L1 hit, broadcast

    // ---- pass 2 (fused): sum exp(o-max), dot(o, S[label]), sum(S[label]) ----
    const float4* s4 = (const float4*)(S + (size_t)label * KK);
    float se = 0.f, dot_os = 0.f, sum_s = 0.f;
    for (int i = tid; i < KK / 4; i += NTHR) {
        float4 o  = o4[i];                    // L1/L2 re-read
        float4 sv = __ldcs(&s4[i]);           // stream
        se += expf(o.x - omax_b) + expf(o.y - omax_b) +
              expf(o.z - omax_b) + expf(o.w - omax_b);
        dot_os += o.x * sv.x + o.y * sv.y + o.z * sv.z + o.w * sv.w;
        sum_s  += sv.x + sv.y + sv.z + sv.w;
    }
    sf0[tid] = se; sf1[tid] = dot_os; sf2[tid] = sum_s;
    __syncthreads();
    for (int s = NTHR / 2; s > 0; s >>= 1) {
        if (tid < s) {
            sf0[tid] += sf0[tid + s];
            sf1[tid] += sf1[tid + s];
            sf2[tid] += sf2[tid + s];
        }
        __syncthreads();
    }

    if (tid == 0) {
        float mls = omax_b + logf(sf0[0]);
        // sum_t = 1, (o.t) = o[label]
        g_hard[b] = (double)o_lab - (double)mls;
        g_soft[b] = (double)sf1[0] - (double)mls * (double)sf2[0];
        s_mls     = mls;
        s_correct = (o_lab == omax_b) ? 1 : 0;   // pred == label
    }
    __syncthreads();

    // ---- sparse scatter (expected ~0-2 rows across the whole batch) ----
    if (s_correct) {
        const float mls = s_mls;
        const float* o = outp + (size_t)b * KK;
        float* dst = out_st + (size_t)label * KK;
        for (int k = tid; k < KK; k += NTHR)
            atomicAdd(&dst[k], expf(o[k] - mls));
        if (tid == 0)
            atomicAdd(&out_count[label], 1.0f);
    }
}

// ---------------- bulk state copy ----------------
// dst_st = out + 1 is 4-byte offset from 16B alignment. Peel first 3 floats
// so stores become STG.128. Runs BEFORE k_rows so the scatter lands on the
// copied data.
#define COPY_BLOCKS 2368           // 148 SMs * 16 blocks
#define COPY_THR    256
__global__ void __launch_bounds__(COPY_THR) k_copy(const float* __restrict__ s_t,
                                                   const float* __restrict__ cnt,
                                                   float* __restrict__ dst_st,
                                                   float* __restrict__ dst_cnt) {
    const long long N  = (long long)KK * KK;      // 67108864
    const long long N4 = (N - 3) >> 2;            // aligned float4 stores

    long long gid    = (long long)blockIdx.x * COPY_THR + threadIdx.x;
    long long stride = (long long)COPY_BLOCKS * COPY_THR;

    if (gid == 0) {
        dst_st[0] = s_t[0];
        dst_st[1] = s_t[1];
        dst_st[2] = s_t[2];
    }

    float4* d4 = (float4*)(dst_st + 3);           // 16B-aligned
    const float* s = s_t + 3;
    for (long long i = gid; i < N4; i += stride) {
        long long k = i << 2;
        float4 v;
        v.x = s[k + 0];
        v.y = s[k + 1];
        v.z = s[k + 2];
        v.w = s[k + 3];
        d4[i] = v;
    }
    // remaining scalar tail elements
    for (long long k = 3 + (N4 << 2) + gid; k < N; k += stride)
        dst_st[k] = s_t[k];

    // count copy (K elements) spread across the grid
    for (long long k = gid; k < KK; k += stride)
        dst_cnt[k] = cnt[k];
}

// ---------------- final loss reduction (1 block) ----------------
__global__ void __launch_bounds__(NTHR) k_loss(float* __restrict__ out_loss) {
    const int tid = threadIdx.x;
    __shared__ double sh[NTHR];
    __shared__ double ss[NTHR];
    double h = 0.0, s = 0.0;
    for (int i = tid; i < BB; i += NTHR) {
        h += g_hard[i];
        s += g_soft[i];
    }
    sh[tid] = h; ss[tid] = s;
    __syncthreads();
    for (int st = NTHR / 2; st > 0; st >>= 1) {
        if (tid < st) { sh[tid] += sh[tid + st]; ss[tid] += ss[tid + st]; }
        __syncthreads();
    }
    if (tid == 0) {
        double ce_hard = -sh[0] / (double)BB;
        double ce_soft = -ss[0] / (double)BB;
        out_loss[0] = (float)(0.5 * ce_hard + 0.5 * ce_soft);
    }
}

extern "C" void kernel_launch(void* const* d_in, const int* in_sizes, int n_in,
                              void* d_out, int out_size) {
    const float* outputs = (const float*)d_in[0];   // [B, K]
    const float* targets = (const float*)d_in[1];   // [B, K] one-hot
    const float* S       = (const float*)d_in[2];   // [K, K]
    const float* S_t     = (const float*)d_in[3];   // [K, K]
    const float* count   = (const float*)d_in[4];   // [K, 1]

    float* out       = (float*)d_out;
    float* out_loss  = out;                              // [1]
    float* out_st    = out + 1;                          // [K*K]
    float* out_count = out + 1 + (size_t)KK * KK;        // [K]

    // copy first: k_rows' embedded scatter adds on top of the copied S_t
    k_copy<<<COPY_BLOCKS, COPY_THR>>>(S_t, count, out_st, out_count);
    k_rows<<<BB, NTHR>>>(outputs, targets, S, out_st, out_count);
    k_loss<<<1, NTHR>>>(out_loss);
}